// round 16
// baseline (speedup 1.0000x reference)
#include <cuda_runtime.h>

// Problem constants
#define BB 64
#define SS 32
#define FF 768
#define UU 768
#define RR (BB*SS)          // 2048 (b,s) rows
#define NSPLIT 512          // VF

// persistent recurrence: 2 independent groups (b-halves), 148 blocks each
#define NGRP 2
#define GBLK 148            // blocks per group (one per SM)
#define NBLK (NGRP*GBLK)    // 296 total, 2 CTAs/SM co-resident
#define NTASK 144           // tasks per group: 12 jt x 4 bt x 3 kk
#define JT 12               // j-tiles of 64
#define BT 4                // b-tiles of 8 (within the 32-b group half)
#define BTILE 8
#define KSPL 3
#define UTH (UU/KSPL)       // 256
#define NUSUB 8             // u-sub-chunks per block (512 thr = 64 j x 8 us)
#define UCH (UTH/NUSUB)     // 32
#define NTILE (JT*BT)       // 48 tiles per group
#define NROUND (SS*6)       // 192

// sensory decomposition
#define RTILE 8
#define FSPLIT 8
#define FCH (FF/FSPLIT)     // 96

// ---------------- static device scratch (no allocation allowed) ----------------
__device__ float4 g_P [UU*UU];   // unfold params (sig/2, -sig*mu/2, w/2, w*erev/2), [u][j]
__device__ float4 g_PS[FF*UU];   // sensory params, same pack, [f][j]
__device__ float  g_CN[UU];      // per-j const: sum w*erev/2 (rec + sensory)
__device__ float  g_CD[UU];      // per-j const: sum w/2       (rec + sensory)
__device__ float  g_X [RR*FF];   // scaled fused input, [r][f]
__device__ float  g_SN[RR*UU];   // sensory numerator + consts
__device__ float  g_SD[RR*UU];   // sensory denominator + consts
__device__ float  g_rts[RR];     // UNFOLDS / elapsed(b,s)
__device__ float2 g_PT[NGRP][KSPL][NTILE][512]; // cross-block u-partials
__device__ unsigned g_arrive[NGRP];    // per-group grid-barrier monotonic counters

__device__ __forceinline__ float tanhf_fast(float x){
    float y; asm("tanh.approx.f32 %0, %1;":"=f"(y):"f"(x)); return y;
}
__device__ __forceinline__ float2 ldcg2(const float2* p){
    float2 v; asm volatile("ld.global.cg.v2.f32 {%0,%1}, [%2];"
                           :"=f"(v.x),"=f"(v.y):"l"(p)); return v;
}
__device__ __forceinline__ unsigned ldcgu(const unsigned* p){
    unsigned v; asm volatile("ld.global.cg.u32 %0, [%1];":"=r"(v):"l"(p)); return v;
}

// ---------------- prep: fold parameters (tanh form) ----------------
// sigmoid(sig*(x-mu)) = 0.5 + 0.5*tanh((sig/2)*x - sig*mu/2)
__global__ void prep_params(const float* __restrict__ s_sig, const float* __restrict__ s_mu,
                            const float* __restrict__ s_w,   const float* __restrict__ s_erev,
                            const float* __restrict__ r_sig, const float* __restrict__ r_mu,
                            const float* __restrict__ r_w,   const float* __restrict__ r_erev){
    int i = blockIdx.x*blockDim.x + threadIdx.x;
    if (i < UU*UU){
        float sg = r_sig[i], m = r_mu[i], w = r_w[i], e = r_erev[i];
        g_P[i]  = make_float4(0.5f*sg, -0.5f*sg*m, 0.5f*w, 0.5f*w*e);
        sg = s_sig[i]; m = s_mu[i]; w = s_w[i]; e = s_erev[i];
        g_PS[i] = make_float4(0.5f*sg, -0.5f*sg*m, 0.5f*w, 0.5f*w*e);
    }
}

// ---------------- prep: per-j constant halves ----------------
__global__ void prep_const(const float* __restrict__ r_w, const float* __restrict__ r_erev,
                           const float* __restrict__ s_w, const float* __restrict__ s_erev){
    int j = blockIdx.x*blockDim.x + threadIdx.x;
    if (j >= UU) return;
    float cn = 0.f, cd = 0.f;
    for (int u = 0; u < UU; u++){
        float w = r_w[u*UU + j], e = r_erev[u*UU + j];
        cn += 0.5f*w*e; cd += 0.5f*w;
    }
    for (int f = 0; f < FF; f++){
        float w = s_w[f*UU + j], e = s_erev[f*UU + j];
        cn += 0.5f*w*e; cd += 0.5f*w;
    }
    g_CN[j] = cn; g_CD[j] = cd;
}

// ---------------- prep: fused+scaled input, rel-ts, counters ----------------
__global__ void prep_misc(const float* __restrict__ fv, const float* __restrict__ fi,
                          const float* __restrict__ ts,
                          const float* __restrict__ iw, const float* __restrict__ ib){
    int i = blockIdx.x*blockDim.x + threadIdx.x;
    if (i < RR*FF){
        int r = i / FF, f = i - r*FF;
        float v = (f < NSPLIT) ? fv[r*NSPLIT + f] : fi[r*(FF-NSPLIT) + (f - NSPLIT)];
        g_X[i] = fmaf(v, iw[f], ib[f]);
    }
    if (i < NGRP) g_arrive[i] = 0u;
    if (i < RR){
        int b = i / SS, s = i - b*SS;
        g_rts[i] = 6.0f / (ts[b*(SS+1)+s+1] - ts[b*(SS+1)+s]);
    }
}

// ---------------- sensory synapse pass (8 rows per thread, tanh) ----------------
// block 256 = 32 j-lanes x 8 f-chunks; grid (UU/32, RR/RTILE) = (24, 256)
__global__ void __launch_bounds__(256) sensory_kernel(){
    __shared__ float  sx[FF*RTILE];            // x transposed: sx[f*8+rr]
    __shared__ float2 sred[FSPLIT][32][RTILE];

    int tid = threadIdx.x;
    int jj = tid & 31, fs = tid >> 5;
    int j  = blockIdx.x*32 + jj;
    int r0 = blockIdx.y*RTILE;

    for (int i = tid; i < RTILE*FF; i += 256){
        int rr = i / FF, f = i - rr*FF;
        sx[f*RTILE + rr] = g_X[(r0+rr)*FF + f];
    }
    __syncthreads();

    float nn[RTILE], dd[RTILE];
    #pragma unroll
    for (int t = 0; t < RTILE; t++){ nn[t] = 0.f; dd[t] = 0.f; }

    int fbase = fs*FCH;
    const float4* __restrict__ sx4 = (const float4*)sx;
    #pragma unroll 2
    for (int ff = 0; ff < FCH; ff++){
        int f = fbase + ff;
        float4 p  = __ldg(&g_PS[f*UU + j]);
        float4 xa = sx4[2*f], xb = sx4[2*f + 1];   // broadcast LDS.128
        float xv[RTILE] = {xa.x, xa.y, xa.z, xa.w, xb.x, xb.y, xb.z, xb.w};
        #pragma unroll
        for (int t = 0; t < RTILE; t++){
            float th = tanhf_fast(fmaf(p.x, xv[t], p.y));
            nn[t] = fmaf(p.w, th, nn[t]);
            dd[t] = fmaf(p.z, th, dd[t]);
        }
    }
    #pragma unroll
    for (int t = 0; t < RTILE; t++) sred[fs][jj][t] = make_float2(nn[t], dd[t]);
    __syncthreads();

    if (fs == 0){
        #pragma unroll
        for (int k = 1; k < FSPLIT; k++)
            #pragma unroll
            for (int t = 0; t < RTILE; t++){
                float2 pr = sred[k][jj][t];
                nn[t] += pr.x; dd[t] += pr.y;
            }
        float cn = g_CN[j], cd = g_CD[j];
        #pragma unroll
        for (int t = 0; t < RTILE; t++){
            g_SN[(r0+t)*UU + j] = nn[t] + cn;
            g_SD[(r0+t)*UU + j] = cd + dd[t];
        }
    }
}

// ---------------- persistent recurrence: smem-resident v, ONE barrier/round ----------------
// 296 blocks x 512 thr = 2 CTAs/SM, groups on b-halves.
// Block (jt,bt,kk): produces partials for (64 j of jt) x (8 b of bt) over u-third kk;
// consumes v-slice (u in third kk) x (8 b of bt), kept in smem across all rounds and
// recomputed redundantly (identical FP order) by all 12 jt-replicas after the barrier.
__global__ void __launch_bounds__(512, 2) recurrence_kernel(
        const float* __restrict__ cm, const float* __restrict__ gleak,
        const float* __restrict__ vleak, const float* __restrict__ ow,
        const float* __restrict__ ob, float* __restrict__ hout){
    __shared__ float  sv[UTH*BTILE];           // persistent v slice: sv[u_local*8+bb]
    __shared__ float2 sred[NUSUB][BTILE][64];  // per-us partials

    const int tid = threadIdx.x;
    const int gid = blockIdx.x / GBLK;         // group 0 or 1
    const int lid = blockIdx.x % GBLK;         // block within group
    const bool work = (lid < NTASK);
    const int jj = tid & 63;                   // j-lane within 64-wide tile
    const int us = tid >> 6;                   // u-sub-chunk 0..7
    const int jt = work ? (lid % JT) : 0;
    const int bt = work ? ((lid / JT) % BT) : 0;
    const int kk = work ? (lid / NTILE) : 0;
    const int tile = bt*JT + jt;
    const int j  = jt*64 + jj;
    const int b0 = gid*32 + bt*BTILE;
    const bool writer = (jt == 0);

    // epilogue per-thread fixed (u,b) quartet: i = tid + q*512
    float cmu[4], glu[4], glvu[4], owu[4], obu[4];
    int ugq[4], bbq[4], tq[4], offq[4];
    #pragma unroll
    for (int q = 0; q < 4; q++){
        int i = tid + q*512;
        int ul = i >> 3, bb = i & 7;
        int ug = kk*UTH + ul;
        ugq[q] = ug; bbq[q] = bb;
        tq[q]  = bt*JT + (ug >> 6);            // source tile for this u
        offq[q]= bb*64 + (ug & 63);
        cmu[q] = __ldg(&cm[ug]);
        glu[q] = __ldg(&gleak[ug]);
        glvu[q]= glu[q] * __ldg(&vleak[ug]);
        owu[q] = __ldg(&ow[ug]);
        obu[q] = __ldg(&ob[ug]);
    }

    // init persistent v = 0
    for (int i = tid; i < UTH*BTILE; i += 512) sv[i] = 0.0f;
    __syncthreads();

    unsigned* const arrive = &g_arrive[gid];

    for (int r = 0; r < NROUND; r++){
        const int s = r / 6;
        const int write_h = ((r % 6) == 5);

        if (work){
            float nn[BTILE], dd[BTILE];
            #pragma unroll
            for (int t = 0; t < BTILE; t++){ nn[t] = 0.f; dd[t] = 0.f; }

            const int ubase = kk*UTH + us*UCH;
            const int ul0 = us*UCH;
            const float4* __restrict__ sv4 = (const float4*)sv;
            #pragma unroll 4
            for (int uu = 0; uu < UCH; uu++){
                float4 p  = __ldg(&g_P[(ubase + uu)*UU + j]);
                int ul = ul0 + uu;
                float4 va = sv4[2*ul], vb = sv4[2*ul + 1];   // broadcast LDS.128
                float vv[BTILE] = {va.x, va.y, va.z, va.w, vb.x, vb.y, vb.z, vb.w};
                #pragma unroll
                for (int t = 0; t < BTILE; t++){
                    float th = tanhf_fast(fmaf(p.x, vv[t], p.y));
                    nn[t] = fmaf(p.w, th, nn[t]);
                    dd[t] = fmaf(p.z, th, dd[t]);
                }
            }
            #pragma unroll
            for (int t = 0; t < BTILE; t++) sred[us][t][jj] = make_float2(nn[t], dd[t]);
        }
        __syncthreads();

        if (work){
            // in-block reduce: thread o = (bo, jo) owns partial (j = jt*64+jo, b = b0+bo)
            const int jo = tid & 63, bo = tid >> 6;
            float2 acc = sred[0][bo][jo];
            #pragma unroll
            for (int k = 1; k < NUSUB; k++){
                float2 pr = sred[k][bo][jo];
                acc.x += pr.x; acc.y += pr.y;
            }
            g_PT[gid][kk][tile][tid] = acc;
            __threadfence();
        }
        __syncthreads();

        // ONE grid barrier per round (per group, monotonic)
        if (tid == 0){
            atomicAdd(arrive, 1u);
            unsigned target = (unsigned)(r + 1) * GBLK;
            while (ldcgu(arrive) < target) __nanosleep(64);
        }
        __syncthreads();

        if (work){
            // rebuild own v-slice from published partials (identical order in all replicas)
            #pragma unroll
            for (int q = 0; q < 4; q++){
                float2 p0 = ldcg2(&g_PT[gid][0][tq[q]][offq[q]]);
                float2 p1 = ldcg2(&g_PT[gid][1][tq[q]][offq[q]]);
                float2 p2 = ldcg2(&g_PT[gid][2][tq[q]][offq[q]]);
                int bb = bbq[q], ug = ugq[q];
                int rrow = (b0 + bb)*SS + s;
                float num = p0.x + p1.x + p2.x + __ldg(&g_SN[rrow*UU + ug]);
                float den = p0.y + p1.y + p2.y + __ldg(&g_SD[rrow*UU + ug]);
                float cmt = cmu[q] * g_rts[rrow];
                int slot = (tid + q*512);      // == ul*8+bb by construction
                float vold = sv[slot];
                float vnew = (cmt*vold + glvu[q] + num) / (cmt + glu[q] + den + 1e-8f);
                sv[slot] = vnew;
                if (write_h && writer)
                    hout[rrow*UU + ug] = fmaf(vnew, owu[q], obu[q]);
            }
        }
        __syncthreads();
    }
}

// ---------------- regressor head: LeakyReLU MLP ----------------
__global__ void __launch_bounds__(128) head_kernel(
        const float* __restrict__ hseq,
        const float* __restrict__ W1, const float* __restrict__ b1,
        const float* __restrict__ W2, const float* __restrict__ b2,
        float* __restrict__ pose){
    __shared__ float sh[UU];
    __shared__ float hid[128];
    int r = blockIdx.x;
    int t = threadIdx.x;
    const float* hr = hseq + r*UU;
    for (int u = t; u < UU; u += 128) sh[u] = hr[u];
    __syncthreads();
    float acc = b1[t];
    #pragma unroll 4
    for (int u = 0; u < UU; u++)
        acc = fmaf(sh[u], __ldg(&W1[u*128 + t]), acc);
    acc = acc > 0.0f ? acc : 0.1f*acc;         // LeakyReLU(0.1)
    hid[t] = acc;
    __syncthreads();
    if (t < 6){
        float a = b2[t];
        #pragma unroll 4
        for (int k = 0; k < 128; k++)
            a = fmaf(hid[k], __ldg(&W2[k*6 + t]), a);
        pose[r*6 + t] = a;
    }
}

// ---------------- launch ----------------
extern "C" void kernel_launch(void* const* d_in, const int* in_sizes, int n_in,
                              void* d_out, int out_size){
    const float* fv     = (const float*)d_in[0];
    // d_in[1] fv_alter (unused), d_in[3] dec (unused)
    const float* fi     = (const float*)d_in[2];
    const float* ts     = (const float*)d_in[4];
    const float* iw     = (const float*)d_in[5];
    const float* ib     = (const float*)d_in[6];
    const float* s_mu   = (const float*)d_in[7];
    const float* s_sig  = (const float*)d_in[8];
    const float* s_w    = (const float*)d_in[9];
    const float* s_erev = (const float*)d_in[10];
    const float* r_mu   = (const float*)d_in[11];
    const float* r_sig  = (const float*)d_in[12];
    const float* r_w    = (const float*)d_in[13];
    const float* r_erev = (const float*)d_in[14];
    const float* gleak  = (const float*)d_in[15];
    const float* vleak  = (const float*)d_in[16];
    const float* cm     = (const float*)d_in[17];
    const float* ow     = (const float*)d_in[18];
    const float* ob     = (const float*)d_in[19];
    const float* W1     = (const float*)d_in[20];
    const float* b1     = (const float*)d_in[21];
    const float* W2     = (const float*)d_in[22];
    const float* b2     = (const float*)d_in[23];

    float* pose = (float*)d_out;               // (B,1,S,6) = 12288 floats
    float* hseq = (float*)d_out + BB*SS*6;     // (B,S,U)

    prep_params<<<(UU*UU + 255)/256, 256>>>(s_sig, s_mu, s_w, s_erev,
                                            r_sig, r_mu, r_w, r_erev);
    prep_const<<<(UU + 255)/256, 256>>>(r_w, r_erev, s_w, s_erev);
    prep_misc<<<(RR*FF + 255)/256, 256>>>(fv, fi, ts, iw, ib);
    sensory_kernel<<<dim3(UU/32, RR/RTILE), 256>>>();

    recurrence_kernel<<<NBLK, 512>>>(cm, gleak, vleak, ow, ob, hseq);

    head_kernel<<<RR, 128>>>(hseq, W1, b1, W2, b2, pose);
}

// round 17
// speedup vs baseline: 1.0336x; 1.0336x over previous
#include <cuda_runtime.h>

// Problem constants
#define BB 64
#define SS 32
#define FF 768
#define UU 768
#define RR (BB*SS)          // 2048 (b,s) rows
#define NSPLIT 512          // VF

// persistent recurrence: 2 independent groups (b-halves), 148 blocks each
#define NGRP 2
#define GBLK 148            // blocks per group (one per SM)
#define NBLK (NGRP*GBLK)    // 296 total, 2 CTAs/SM co-resident
#define NTASK 144           // tasks per group: 12 jt x 4 bt x 3 kk
#define JT 12               // j-tiles of 64
#define BT 4                // b-tiles of 8 (within the 32-b group half)
#define BTILE 8
#define KSPL 3
#define UTH (UU/KSPL)       // 256
#define NUSUB 8             // u-sub-chunks per block (512 thr = 64 j x 8 us)
#define UCH (UTH/NUSUB)     // 32
#define NTILE (JT*BT)       // 48 tiles per group
#define NROUND (SS*6)       // 192

// sensory decomposition
#define RTILE 8
#define FSPLIT 8
#define FCH (FF/FSPLIT)     // 96

// ---------------- static device scratch (no allocation allowed) ----------------
__device__ float4 g_P [UU*UU];   // unfold params (sig/2, -sig*mu/2, w/2, w*erev/2), [u][j]
__device__ float4 g_PS[FF*UU];   // sensory params, same pack, [f][j]
__device__ float  g_CN[UU];      // per-j const: sum w*erev/2 (rec + sensory)
__device__ float  g_CD[UU];      // per-j const: sum w/2       (rec + sensory)
__device__ float  g_X [RR*FF];   // scaled fused input, [r][f]
__device__ float  g_SN[RR*UU];   // sensory numerator + consts
__device__ float  g_SD[RR*UU];   // sensory denominator + consts
__device__ float  g_V [2][BB*UU];// double-buffered recurrent state
__device__ float  g_rts[RR];     // UNFOLDS / elapsed(b,s)
__device__ float2 g_PT[NGRP][KSPL][NTILE][512]; // cross-block u-partials
__device__ int    g_cnt [NGRP][NTILE];  // per-tile monotonic arrival counters
__device__ int    g_flag[NGRP][NTILE];  // per-tile round stamp: v_{flag} available

__device__ __forceinline__ float tanhf_fast(float x){
    float y; asm("tanh.approx.f32 %0, %1;":"=f"(y):"f"(x)); return y;
}
__device__ __forceinline__ float ldcgf(const float* p){
    float v; asm volatile("ld.global.cg.f32 %0, [%1];":"=f"(v):"l"(p)); return v;
}
__device__ __forceinline__ float2 ldcg2(const float2* p){
    float2 v; asm volatile("ld.global.cg.v2.f32 {%0,%1}, [%2];"
                           :"=f"(v.x),"=f"(v.y):"l"(p)); return v;
}
__device__ __forceinline__ int ldcgi(const int* p){
    int v; asm volatile("ld.global.cg.s32 %0, [%1];":"=r"(v):"l"(p)); return v;
}

// ---------------- prep: fold parameters (tanh form) ----------------
// sigmoid(sig*(x-mu)) = 0.5 + 0.5*tanh((sig/2)*x - sig*mu/2)
__global__ void prep_params(const float* __restrict__ s_sig, const float* __restrict__ s_mu,
                            const float* __restrict__ s_w,   const float* __restrict__ s_erev,
                            const float* __restrict__ r_sig, const float* __restrict__ r_mu,
                            const float* __restrict__ r_w,   const float* __restrict__ r_erev){
    int i = blockIdx.x*blockDim.x + threadIdx.x;
    if (i < UU*UU){
        float sg = r_sig[i], m = r_mu[i], w = r_w[i], e = r_erev[i];
        g_P[i]  = make_float4(0.5f*sg, -0.5f*sg*m, 0.5f*w, 0.5f*w*e);
        sg = s_sig[i]; m = s_mu[i]; w = s_w[i]; e = s_erev[i];
        g_PS[i] = make_float4(0.5f*sg, -0.5f*sg*m, 0.5f*w, 0.5f*w*e);
    }
}

// ---------------- prep: per-j constant halves ----------------
__global__ void prep_const(const float* __restrict__ r_w, const float* __restrict__ r_erev,
                           const float* __restrict__ s_w, const float* __restrict__ s_erev){
    int j = blockIdx.x*blockDim.x + threadIdx.x;
    if (j >= UU) return;
    float cn = 0.f, cd = 0.f;
    for (int u = 0; u < UU; u++){
        float w = r_w[u*UU + j], e = r_erev[u*UU + j];
        cn += 0.5f*w*e; cd += 0.5f*w;
    }
    for (int f = 0; f < FF; f++){
        float w = s_w[f*UU + j], e = s_erev[f*UU + j];
        cn += 0.5f*w*e; cd += 0.5f*w;
    }
    g_CN[j] = cn; g_CD[j] = cd;
}

// ---------------- prep: fused+scaled input, rel-ts, state/counters/flags ----------------
__global__ void prep_misc(const float* __restrict__ fv, const float* __restrict__ fi,
                          const float* __restrict__ ts,
                          const float* __restrict__ iw, const float* __restrict__ ib){
    int i = blockIdx.x*blockDim.x + threadIdx.x;
    if (i < RR*FF){
        int r = i / FF, f = i - r*FF;
        float v = (f < NSPLIT) ? fv[r*NSPLIT + f] : fi[r*(FF-NSPLIT) + (f - NSPLIT)];
        g_X[i] = fmaf(v, iw[f], ib[f]);
    }
    if (i < BB*UU) g_V[0][i] = 0.0f;
    if (i < NGRP*NTILE){
        ((int*)g_cnt)[i]  = 0;
        ((int*)g_flag)[i] = 0;
    }
    if (i < RR){
        int b = i / SS, s = i - b*SS;
        g_rts[i] = 6.0f / (ts[b*(SS+1)+s+1] - ts[b*(SS+1)+s]);
    }
}

// ---------------- sensory synapse pass (8 rows per thread, tanh) ----------------
// block 256 = 32 j-lanes x 8 f-chunks; grid (UU/32, RR/RTILE) = (24, 256)
__global__ void __launch_bounds__(256) sensory_kernel(){
    __shared__ float  sx[FF*RTILE];            // x transposed: sx[f*8+rr]
    __shared__ float2 sred[FSPLIT][32][RTILE];

    int tid = threadIdx.x;
    int jj = tid & 31, fs = tid >> 5;
    int j  = blockIdx.x*32 + jj;
    int r0 = blockIdx.y*RTILE;

    for (int i = tid; i < RTILE*FF; i += 256){
        int rr = i / FF, f = i - rr*FF;
        sx[f*RTILE + rr] = g_X[(r0+rr)*FF + f];
    }
    __syncthreads();

    float nn[RTILE], dd[RTILE];
    #pragma unroll
    for (int t = 0; t < RTILE; t++){ nn[t] = 0.f; dd[t] = 0.f; }

    int fbase = fs*FCH;
    const float4* __restrict__ sx4 = (const float4*)sx;
    #pragma unroll 2
    for (int ff = 0; ff < FCH; ff++){
        int f = fbase + ff;
        float4 p  = __ldg(&g_PS[f*UU + j]);
        float4 xa = sx4[2*f], xb = sx4[2*f + 1];   // broadcast LDS.128
        float xv[RTILE] = {xa.x, xa.y, xa.z, xa.w, xb.x, xb.y, xb.z, xb.w};
        #pragma unroll
        for (int t = 0; t < RTILE; t++){
            float th = tanhf_fast(fmaf(p.x, xv[t], p.y));
            nn[t] = fmaf(p.w, th, nn[t]);
            dd[t] = fmaf(p.z, th, dd[t]);
        }
    }
    #pragma unroll
    for (int t = 0; t < RTILE; t++) sred[fs][jj][t] = make_float2(nn[t], dd[t]);
    __syncthreads();

    if (fs == 0){
        #pragma unroll
        for (int k = 1; k < FSPLIT; k++)
            #pragma unroll
            for (int t = 0; t < RTILE; t++){
                float2 pr = sred[k][jj][t];
                nn[t] += pr.x; dd[t] += pr.y;
            }
        float cn = g_CN[j], cd = g_CD[j];
        #pragma unroll
        for (int t = 0; t < RTILE; t++){
            g_SN[(r0+t)*UU + j] = nn[t] + cn;
            g_SD[(r0+t)*UU + j] = dd[t] + cd;
        }
    }
}

// ---------------- persistent recurrence: per-tile dataflow flags, no grid barrier ----------------
// 296 blocks x 512 thr = 2 CTAs/SM. Group g = bid/148 owns b in [g*32, g*32+32).
// Block (jt,bt,kk) waits only on the 4 tiles covering its u-third (+ own tile for
// g_PT slot reuse), each stamped with the round whose v it has published.
__global__ void __launch_bounds__(512, 2) recurrence_kernel(
        const float* __restrict__ cm, const float* __restrict__ gleak,
        const float* __restrict__ vleak, const float* __restrict__ ow,
        const float* __restrict__ ob, float* __restrict__ hout){
    __shared__ float  sv[UTH*BTILE];           // v third, transposed: sv[u_local*8+bb]
    __shared__ float2 sred[NUSUB][BTILE][64];  // per-us partials
    __shared__ int    s_last;

    const int tid = threadIdx.x;
    const int gid = blockIdx.x / GBLK;         // group 0 or 1
    const int lid = blockIdx.x % GBLK;         // block within group
    if (lid >= NTASK) return;                  // idle blocks exit (no global barrier)
    const int jj = tid & 63;                   // j-lane within 64-wide tile
    const int us = tid >> 6;                   // u-sub-chunk 0..7
    const int jt = lid % JT;
    const int bt = (lid / JT) % BT;
    const int kk = lid / NTILE;
    const int tile = bt*JT + jt;
    const int j  = jt*64 + jj;
    const int b0 = gid*32 + bt*BTILE;
    const int k1 = (kk+1)%3, k2 = (kk+2)%3;

    // wait set: 4 source tiles (v for u-third kk) + own tile (g_PT slot consumed)
    int wtile;
    if (tid < 4)      wtile = bt*JT + kk*4 + tid;
    else if (tid == 4) wtile = tile;
    const int* const fptr = (tid < 5) ? &g_flag[gid][wtile] : 0;

    // epilogue-role indices: thread o <-> (jo, bo)
    const int jo = tid & 63, bo = tid >> 6;
    const int je = jt*64 + jo;
    const int be = b0 + bo;

    // per-j epilogue constants (loop-invariant)
    const float cmj = __ldg(&cm[je]);
    const float gl  = __ldg(&gleak[je]);
    const float glv = gl * __ldg(&vleak[je]);
    const float owj = __ldg(&ow[je]);
    const float obj = __ldg(&ob[je]);

    for (int r = 0; r < NROUND; r++){
        const int s = r / 6;
        const int pin = r & 1, pout = pin ^ 1;
        const int write_h = ((r % 6) == 5);

        // dataflow wait: sources have published v_r; own partial slot free
        if (tid < 5){
            while (ldcgi(fptr) < r) __nanosleep(32);
        }
        __syncthreads();

        // stage this u-third of v for 8 batches (L2-coherent reads)
        {
            const float* vg = &g_V[pin][b0*UU + kk*UTH];
            #pragma unroll
            for (int i = tid; i < BTILE*UTH; i += 512){
                int bb = i >> 8, u = i & 255;        // UTH=256
                sv[u*BTILE + bb] = ldcgf(&vg[bb*UU + u]);
            }
        }
        __syncthreads();

        {
            float nn[BTILE], dd[BTILE];
            #pragma unroll
            for (int t = 0; t < BTILE; t++){ nn[t] = 0.f; dd[t] = 0.f; }

            const int ubase = kk*UTH + us*UCH;
            const int ul0 = us*UCH;
            const float4* __restrict__ sv4 = (const float4*)sv;
            #pragma unroll 4
            for (int uu = 0; uu < UCH; uu++){
                float4 p  = __ldg(&g_P[(ubase + uu)*UU + j]);
                int ul = ul0 + uu;
                float4 va = sv4[2*ul], vb = sv4[2*ul + 1];   // broadcast LDS.128
                float vv[BTILE] = {va.x, va.y, va.z, va.w, vb.x, vb.y, vb.z, vb.w};
                #pragma unroll
                for (int t = 0; t < BTILE; t++){
                    float th = tanhf_fast(fmaf(p.x, vv[t], p.y));
                    nn[t] = fmaf(p.w, th, nn[t]);
                    dd[t] = fmaf(p.z, th, dd[t]);
                }
            }
            #pragma unroll
            for (int t = 0; t < BTILE; t++) sred[us][t][jj] = make_float2(nn[t], dd[t]);
        }
        __syncthreads();

        // in-block reduce: thread o owns output (jo, bo); publish partial
        float2 acc = sred[0][bo][jo];
        #pragma unroll
        for (int k = 1; k < NUSUB; k++){
            float2 pr = sred[k][bo][jo];
            acc.x += pr.x; acc.y += pr.y;
        }
        g_PT[gid][kk][tile][tid] = acc;
        __threadfence();
        __syncthreads();
        if (tid == 0)
            s_last = (atomicAdd(&g_cnt[gid][tile], 1) == r*KSPL + (KSPL-1));
        __syncthreads();

        if (s_last){
            // owner epilogue: combine 3 partials, update v, publish flag
            float2 pa = ldcg2(&g_PT[gid][k1][tile][tid]);
            float2 pb = ldcg2(&g_PT[gid][k2][tile][tid]);
            int rrow = be*SS + s;
            float num = acc.x + pa.x + pb.x + __ldg(&g_SN[rrow*UU + je]);
            float den = acc.y + pa.y + pb.y + __ldg(&g_SD[rrow*UU + je]);
            float cmt = cmj * g_rts[rrow];
            float vold = ldcgf(&g_V[pin][be*UU + je]);
            float vnew = (cmt*vold + glv + num) / (cmt + gl + den + 1e-8f);
            g_V[pout][be*UU + je] = vnew;
            if (write_h)
                hout[rrow*UU + je] = fmaf(vnew, owj, obj);
            __threadfence();
            __syncthreads();
            if (tid == 0)
                asm volatile("st.global.cg.s32 [%0], %1;"
                             :: "l"(&g_flag[gid][tile]), "r"(r + 1) : "memory");
        }
    }
}

// ---------------- regressor head: LeakyReLU MLP ----------------
__global__ void __launch_bounds__(128) head_kernel(
        const float* __restrict__ hseq,
        const float* __restrict__ W1, const float* __restrict__ b1,
        const float* __restrict__ W2, const float* __restrict__ b2,
        float* __restrict__ pose){
    __shared__ float sh[UU];
    __shared__ float hid[128];
    int r = blockIdx.x;
    int t = threadIdx.x;
    const float* hr = hseq + r*UU;
    for (int u = t; u < UU; u += 128) sh[u] = hr[u];
    __syncthreads();
    float acc = b1[t];
    #pragma unroll 4
    for (int u = 0; u < UU; u++)
        acc = fmaf(sh[u], __ldg(&W1[u*128 + t]), acc);
    acc = acc > 0.0f ? acc : 0.1f*acc;         // LeakyReLU(0.1)
    hid[t] = acc;
    __syncthreads();
    if (t < 6){
        float a = b2[t];
        #pragma unroll 4
        for (int k = 0; k < 128; k++)
            a = fmaf(hid[k], __ldg(&W2[k*6 + t]), a);
        pose[r*6 + t] = a;
    }
}

// ---------------- launch ----------------
extern "C" void kernel_launch(void* const* d_in, const int* in_sizes, int n_in,
                              void* d_out, int out_size){
    const float* fv     = (const float*)d_in[0];
    // d_in[1] fv_alter (unused), d_in[3] dec (unused)
    const float* fi     = (const float*)d_in[2];
    const float* ts     = (const float*)d_in[4];
    const float* iw     = (const float*)d_in[5];
    const float* ib     = (const float*)d_in[6];
    const float* s_mu   = (const float*)d_in[7];
    const float* s_sig  = (const float*)d_in[8];
    const float* s_w    = (const float*)d_in[9];
    const float* s_erev = (const float*)d_in[10];
    const float* r_mu   = (const float*)d_in[11];
    const float* r_sig  = (const float*)d_in[12];
    const float* r_w    = (const float*)d_in[13];
    const float* r_erev = (const float*)d_in[14];
    const float* gleak  = (const float*)d_in[15];
    const float* vleak  = (const float*)d_in[16];
    const float* cm     = (const float*)d_in[17];
    const float* ow     = (const float*)d_in[18];
    const float* ob     = (const float*)d_in[19];
    const float* W1     = (const float*)d_in[20];
    const float* b1     = (const float*)d_in[21];
    const float* W2     = (const float*)d_in[22];
    const float* b2     = (const float*)d_in[23];

    float* pose = (float*)d_out;               // (B,1,S,6) = 12288 floats
    float* hseq = (float*)d_out + BB*SS*6;     // (B,S,U)

    prep_params<<<(UU*UU + 255)/256, 256>>>(s_sig, s_mu, s_w, s_erev,
                                            r_sig, r_mu, r_w, r_erev);
    prep_const<<<(UU + 255)/256, 256>>>(r_w, r_erev, s_w, s_erev);
    prep_misc<<<(RR*FF + 255)/256, 256>>>(fv, fi, ts, iw, ib);
    sensory_kernel<<<dim3(UU/32, RR/RTILE), 256>>>();

    recurrence_kernel<<<NBLK, 512>>>(cm, gleak, vleak, ow, ob, hseq);

    head_kernel<<<RR, 128>>>(hseq, W1, b1, W2, b2, pose);
}